// round 15
// baseline (speedup 1.0000x reference)
#include <cuda_runtime.h>
#include <cuda_fp16.h>
#include <cstdint>

#define D_K 1024
#define D_N 1024
#define N_B 32
#define N_T 2048
#define N_M (N_B * N_T)

__device__ __half g_WyT[(size_t)D_N * D_K];     // Wy^T fp16 [n][k]
__device__ float g_hproj[N_B * D_N];
__device__ float g_scores[N_M];
__device__ float g_alpha[N_M];
__device__ float g_rpart[8 * N_B * D_K];

__device__ __forceinline__ void mma_f16(float* c, const unsigned* a,
                                        unsigned b0, unsigned b1) {
    asm volatile(
        "mma.sync.aligned.m16n8k16.row.col.f32.f16.f16.f32 "
        "{%0,%1,%2,%3}, {%4,%5,%6,%7}, {%8,%9}, {%0,%1,%2,%3};\n"
        : "+f"(c[0]), "+f"(c[1]), "+f"(c[2]), "+f"(c[3])
        : "r"(a[0]), "r"(a[1]), "r"(a[2]), "r"(a[3]), "r"(b0), "r"(b1));
}
__device__ __forceinline__ void ldmx4(unsigned* r, unsigned addr) {
    asm volatile("ldmatrix.sync.aligned.m8n8.x4.shared.b16 {%0,%1,%2,%3}, [%4];"
                 : "=r"(r[0]), "=r"(r[1]), "=r"(r[2]), "=r"(r[3]) : "r"(addr));
}
__device__ __forceinline__ void cp16(unsigned dst, const void* src) {
    asm volatile("cp.async.cg.shared.global [%0], [%1], 16;\n" :: "r"(dst), "l"(src));
}
__device__ __forceinline__ void cp_commit() { asm volatile("cp.async.commit_group;\n"); }
template <int N> __device__ __forceinline__ void cp_wait() {
    asm volatile("cp.async.wait_group %0;\n" :: "n"(N));
}
__device__ __forceinline__ void sts128(unsigned dst, unsigned a, unsigned b,
                                       unsigned c, unsigned d) {
    asm volatile("st.shared.v4.b32 [%0], {%1,%2,%3,%4};"
                 :: "r"(dst), "r"(a), "r"(b), "r"(c), "r"(d));
}

// ---- transpose Wy -> WyT fp16 [n][k] -----------------------------------------
__global__ void k_split_wy(const float* __restrict__ Wy) {
    __shared__ float tile[32][33];
    int k = blockIdx.y * 32 + threadIdx.y;
    int n = blockIdx.x * 32 + threadIdx.x;
    tile[threadIdx.y][threadIdx.x] = Wy[(size_t)k * D_N + n];
    __syncthreads();
    int nn = blockIdx.x * 32 + threadIdx.y;
    int kk = blockIdx.y * 32 + threadIdx.x;
    g_WyT[(size_t)nn * D_K + kk] = __float2half_rn(tile[threadIdx.x][threadIdx.y]);
}

// ---- hproj = last_state @ Wh ---------------------------------------------------
__global__ void k_hproj(const float* __restrict__ last, const float* __restrict__ Wh) {
    int b = blockIdx.y;
    int e = blockIdx.x * 256 + threadIdx.x;
    __shared__ float sL[D_K];
    for (int i = threadIdx.x; i < D_K; i += 256) sL[i] = last[b * D_K + i];
    __syncthreads();
    float acc = 0.f;
#pragma unroll 8
    for (int k = 0; k < D_K; ++k) acc += sL[k] * Wh[(size_t)k * D_N + e];
    g_hproj[b * D_N + e] = acc;
}

// ---- fused fp16 GEMM -> scores, A resident in SMEM ------------------------------
// A: 64 rows x 1024 k fp16 = 128 KB, 2048 B rows, chunk swizzle c ^= (row&7).
// B ring: 12 stages x 8 KB (128 n-rows x 32 k, 64 B rows, c ^= ((row>>1)&3)).
// j loop: 64 groups of 4 stages (BK=128); 8 groups per 128-wide N-tile.
#define A_BYTES 131072
#define BSTG 8192
#define NBSTG 12

__device__ __forceinline__ void load_bstage(unsigned sbuf, int n0, int k0, int tid) {
#pragma unroll
    for (int i = 0; i < 2; ++i) {
        int cid = (i << 8) + tid;
        int row = cid >> 2, c = cid & 3;
        unsigned off = row * 64 + ((c ^ ((row >> 1) & 3)) << 4);
        cp16(sbuf + off, g_WyT + (size_t)(n0 + row) * D_K + k0 + c * 8);
    }
}
__device__ __forceinline__ void load_group(unsigned Bb, int slot4, int j, int tid) {
    const int n0 = (j >> 3) << 7;
    const int kb = (j & 7) << 7;
#pragma unroll
    for (int s = 0; s < 4; ++s)
        load_bstage(Bb + (slot4 + s) * BSTG, n0, kb + s * 32, tid);
}
// convert x slice (128 k-cols) of this CTA's 64 rows into resident A smem
__device__ __forceinline__ void conv_sliceA(unsigned Ab, const float* __restrict__ x,
                                            int m0, int sl, int tid) {
#pragma unroll
    for (int i = 0; i < 4; ++i) {
        int idx = (i << 8) + tid;               // 0..1023 : 64 rows x 16 chunks
        int r = idx >> 4, cc = idx & 15;
        int c = (sl << 4) + cc;
        const float4* src = reinterpret_cast<const float4*>(
            x + (size_t)(m0 + r) * D_K + c * 8);
        float4 v0 = src[0], v1 = src[1];
        __half2 h0 = __floats2half2_rn(v0.x, v0.y), h1 = __floats2half2_rn(v0.z, v0.w);
        __half2 h2 = __floats2half2_rn(v1.x, v1.y), h3 = __floats2half2_rn(v1.z, v1.w);
        unsigned dst = Ab + r * 2048 + ((c ^ (r & 7)) << 4);
        sts128(dst, *reinterpret_cast<unsigned*>(&h0), *reinterpret_cast<unsigned*>(&h1),
                    *reinterpret_cast<unsigned*>(&h2), *reinterpret_cast<unsigned*>(&h3));
    }
}

__global__ void __launch_bounds__(256) k_scores(const float* __restrict__ x,
                                                const float* __restrict__ wv) {
    extern __shared__ uint8_t dsm[];
    __shared__ float sScore[2][64];

    const int tid = threadIdx.x, lane = tid & 31, warp = tid >> 5;
    const int wm = warp & 3, wn = warp >> 2;
    const int qr = lane >> 2, qc = (lane & 3) << 1;
    const int m0 = blockIdx.x << 6;
    const int b = m0 >> 11;
    const int g = lane >> 3, lr = lane & 7;

    unsigned sbase;
    asm("{ .reg .u64 t; cvta.to.shared.u64 t, %1; cvt.u32.u64 %0, t; }"
        : "=r"(sbase) : "l"(dsm));
    const unsigned Ab = sbase;
    const unsigned Bb = sbase + A_BYTES;

    // B ldmatrix per-lane offsets (within one 8 KB stage), per k16-substep
    unsigned boff[4][2];
#pragma unroll
    for (int p = 0; p < 4; ++p) {
        int nl = wn * 64 + p * 16 + ((g >> 1) & 1) * 8 + lr;
#pragma unroll
        for (int ks = 0; ks < 2; ++ks) {
            int c = 2 * ks + (g & 1);
            boff[p][ks] = nl * 64 + ((c ^ ((nl >> 1) & 3)) << 4);
        }
    }
    // A ldmatrix: row base + per-k16 chunk offsets within a 256 B j-block
    const int ml = wm * 16 + (g & 1) * 8 + lr;
    const unsigned Ar = Ab + ml * 2048;
    unsigned aoffu[8];
#pragma unroll
    for (int u = 0; u < 8; ++u)
        aoffu[u] = ((2 * u + (g >> 1)) ^ lr) << 4;

    if (tid < 128) (&sScore[0][0])[tid] = 0.f;

    // start B preloads first so cp.async overlaps the conversion LDGs
    load_group(Bb, 0, 0, tid); cp_commit();
    load_group(Bb, 4, 1, tid); cp_commit();
    conv_sliceA(Ab, x, m0, 0, tid);
    conv_sliceA(Ab, x, m0, 1, tid);
    __syncthreads();

    float acc[8][4];
#pragma unroll
    for (int nf = 0; nf < 8; ++nf)
#pragma unroll
        for (int q = 0; q < 4; ++q) acc[nf][q] = 0.f;

#pragma unroll 1
    for (int j = 0; j < 64; ++j) {
        cp_wait<1>();
        __syncthreads();
        if (j < 62) load_group(Bb, ((j + 2) % 3) * 4, j + 2, tid);
        cp_commit();

        const unsigned jA = Ar + ((j & 7) << 8);
        const unsigned sB = Bb + (j % 3) * 4 * BSTG;
#pragma unroll
        for (int st = 0; st < 4; ++st) {
            const unsigned sbst = sB + st * BSTG;
#pragma unroll
            for (int ks = 0; ks < 2; ++ks) {
                unsigned a[4];
                ldmx4(a, jA + aoffu[st * 2 + ks]);
#pragma unroll
                for (int p = 0; p < 4; ++p) {
                    unsigned bb[4];
                    ldmx4(bb, sbst + boff[p][ks]);
                    mma_f16(acc[2 * p],     a, bb[0], bb[1]);
                    mma_f16(acc[2 * p + 1], a, bb[2], bb[3]);
                }
            }
        }

        // convert the A slice needed 2 groups from now (N-tile 0 only)
        if (j + 2 < 8) conv_sliceA(Ab, x, m0, j + 2, tid);

        if ((j & 7) == 7) {                      // N-tile complete
            const int n0 = (j >> 3) << 7;
            float sa = 0.f, sb2 = 0.f;
#pragma unroll
            for (int nf = 0; nf < 8; ++nf) {
                int gcol = n0 + wn * 64 + nf * 8 + qc;
                float hp0 = __ldg(&g_hproj[b * D_N + gcol]);
                float hp1 = __ldg(&g_hproj[b * D_N + gcol + 1]);
                float w0 = __ldg(&wv[gcol]), w1 = __ldg(&wv[gcol + 1]);
                sa  += fmaxf(acc[nf][0] + hp0, 0.f) * w0
                     + fmaxf(acc[nf][1] + hp1, 0.f) * w1;
                sb2 += fmaxf(acc[nf][2] + hp0, 0.f) * w0
                     + fmaxf(acc[nf][3] + hp1, 0.f) * w1;
#pragma unroll
                for (int q = 0; q < 4; ++q) acc[nf][q] = 0.f;
            }
            sa  += __shfl_xor_sync(0xffffffffu, sa, 1);
            sa  += __shfl_xor_sync(0xffffffffu, sa, 2);
            sb2 += __shfl_xor_sync(0xffffffffu, sb2, 1);
            sb2 += __shfl_xor_sync(0xffffffffu, sb2, 2);
            if ((lane & 3) == 0) {
                int r0 = wm * 16 + qr;
                sScore[wn][r0]     += sa;
                sScore[wn][r0 + 8] += sb2;
            }
        }
    }

    __syncthreads();
    if (tid < 64) g_scores[m0 + tid] = sScore[0][tid] + sScore[1][tid];
}

// ---- softmax over T --------------------------------------------------------------
__global__ void k_softmax() {
    int b = blockIdx.x, tid = threadIdx.x;
    __shared__ float red[256];
    float m = -1e30f;
    for (int t = tid; t < N_T; t += 256) m = fmaxf(m, g_scores[b * N_T + t]);
    red[tid] = m; __syncthreads();
    for (int s = 128; s > 0; s >>= 1) {
        if (tid < s) red[tid] = fmaxf(red[tid], red[tid + s]);
        __syncthreads();
    }
    float mx = red[0]; __syncthreads();
    float sum = 0.f;
    for (int t = tid; t < N_T; t += 256) {
        float e = __expf(g_scores[b * N_T + t] - mx);
        g_alpha[b * N_T + t] = e;
        sum += e;
    }
    red[tid] = sum; __syncthreads();
    for (int s = 128; s > 0; s >>= 1) {
        if (tid < s) red[tid] += red[tid + s];
        __syncthreads();
    }
    float inv = 1.0f / red[0];
    for (int t = tid; t < N_T; t += 256) g_alpha[b * N_T + t] *= inv;
}

// ---- r partials (reads x f32) -------------------------------------------------------
__global__ void k_rpart(const float* __restrict__ x) {
    int d = blockIdx.x * 256 + threadIdx.x;
    int b = blockIdx.y, p = blockIdx.z;
    __shared__ float sAl[256];
    sAl[threadIdx.x] = g_alpha[b * N_T + p * 256 + threadIdx.x];
    __syncthreads();
    const float* xp = x + ((size_t)b * N_T + p * 256) * D_K + d;
    float acc = 0.f;
#pragma unroll 8
    for (int i = 0; i < 256; ++i) acc += sAl[i] * xp[(size_t)i * D_K];
    g_rpart[(p * N_B + b) * D_K + d] = acc;
}

// ---- out = relu(r @ Wp + last @ Wx) ---------------------------------------------------
__global__ void k_final(const float* __restrict__ last, const float* __restrict__ Wp,
                        const float* __restrict__ Wx, float* __restrict__ out) {
    int e = blockIdx.x * 256 + threadIdx.x;
    int b = blockIdx.y;
    __shared__ float sR[D_K], sL[D_K];
    for (int i = threadIdx.x; i < D_K; i += 256) {
        float r = 0.f;
#pragma unroll
        for (int p = 0; p < 8; ++p) r += g_rpart[(p * N_B + b) * D_K + i];
        sR[i] = r;
        sL[i] = last[b * D_K + i];
    }
    __syncthreads();
    float acc = 0.f;
#pragma unroll 4
    for (int k = 0; k < D_K; ++k)
        acc += sR[k] * Wp[(size_t)k * D_N + e] + sL[k] * Wx[(size_t)k * D_N + e];
    out[b * D_N + e] = fmaxf(acc, 0.f);
}

// ---- launch ----------------------------------------------------------------------------
extern "C" void kernel_launch(void* const* d_in, const int* in_sizes, int n_in,
                              void* d_out, int out_size) {
    const float* x    = (const float*)d_in[0];
    const float* last = (const float*)d_in[1];
    const float* Wy   = (const float*)d_in[2];
    const float* Wh   = (const float*)d_in[3];
    const float* wv   = (const float*)d_in[4];
    const float* Wp   = (const float*)d_in[5];
    const float* Wx   = (const float*)d_in[6];
    float* out = (float*)d_out;

    const int smem = A_BYTES + NBSTG * BSTG;     // 229376 B
    static bool attr_set = false;
    if (!attr_set) {
        cudaFuncSetAttribute(k_scores, cudaFuncAttributeMaxDynamicSharedMemorySize, smem);
        attr_set = true;
    }

    k_split_wy<<<dim3(32, 32), dim3(32, 32)>>>(Wy);
    k_hproj<<<dim3(4, N_B), 256>>>(last, Wh);
    k_scores<<<N_M / 64, 256, smem>>>(x, wv);
    k_softmax<<<N_B, 256>>>();
    k_rpart<<<dim3(4, N_B, 8), 256>>>(x);
    k_final<<<dim3(4, N_B), 256>>>(last, Wp, Wx, out);
}

// round 16
// speedup vs baseline: 1.1942x; 1.1942x over previous
#include <cuda_runtime.h>
#include <cuda_fp16.h>
#include <cstdint>

#define D_K 1024
#define D_N 1024
#define N_B 32
#define N_T 2048
#define N_M (N_B * N_T)

__device__ __half g_Ah[(size_t)N_M * D_K];      // x in fp16 (written by k_scores prologue)
__device__ __half g_WyT[(size_t)D_N * D_K];     // Wy^T in fp16 [n][k]
__device__ float g_hproj[N_B * D_N];
__device__ float g_scores[N_M];
__device__ float g_alpha[N_M];
__device__ float g_rpart[8 * N_B * D_K];

__device__ __forceinline__ void mma_f16(float* c, const unsigned* a,
                                        unsigned b0, unsigned b1) {
    asm volatile(
        "mma.sync.aligned.m16n8k16.row.col.f32.f16.f16.f32 "
        "{%0,%1,%2,%3}, {%4,%5,%6,%7}, {%8,%9}, {%0,%1,%2,%3};\n"
        : "+f"(c[0]), "+f"(c[1]), "+f"(c[2]), "+f"(c[3])
        : "r"(a[0]), "r"(a[1]), "r"(a[2]), "r"(a[3]), "r"(b0), "r"(b1));
}
__device__ __forceinline__ void ldmx4(unsigned* r, unsigned addr) {
    asm volatile("ldmatrix.sync.aligned.m8n8.x4.shared.b16 {%0,%1,%2,%3}, [%4];"
                 : "=r"(r[0]), "=r"(r[1]), "=r"(r[2]), "=r"(r[3]) : "r"(addr));
}
__device__ __forceinline__ void cp16(unsigned dst, const void* src) {
    asm volatile("cp.async.cg.shared.global [%0], [%1], 16;\n" :: "r"(dst), "l"(src));
}
__device__ __forceinline__ void cp_commit() { asm volatile("cp.async.commit_group;\n"); }
template <int N> __device__ __forceinline__ void cp_wait() {
    asm volatile("cp.async.wait_group %0;\n" :: "n"(N));
}

// ---- transpose Wy -> WyT fp16 [n][k] -----------------------------------------
__global__ void k_split_wy(const float* __restrict__ Wy) {
    __shared__ float tile[32][33];
    int k = blockIdx.y * 32 + threadIdx.y;
    int n = blockIdx.x * 32 + threadIdx.x;
    tile[threadIdx.y][threadIdx.x] = Wy[(size_t)k * D_N + n];
    __syncthreads();
    int nn = blockIdx.x * 32 + threadIdx.y;
    int kk = blockIdx.y * 32 + threadIdx.x;
    g_WyT[(size_t)nn * D_K + kk] = __float2half_rn(tile[threadIdx.x][threadIdx.y]);
}

// ---- hproj = last_state @ Wh ---------------------------------------------------
__global__ void k_hproj(const float* __restrict__ last, const float* __restrict__ Wh) {
    int b = blockIdx.y;
    int e = blockIdx.x * 256 + threadIdx.x;
    __shared__ float sL[D_K];
    for (int i = threadIdx.x; i < D_K; i += 256) sL[i] = last[b * D_K + i];
    __syncthreads();
    float acc = 0.f;
#pragma unroll 8
    for (int k = 0; k < D_K; ++k) acc += sL[k] * Wh[(size_t)k * D_N + e];
    g_hproj[b * D_N + e] = acc;
}

// ---- fused fp16 GEMM -> scores (in-kernel x->fp16 conversion) --------------------
// Stage (16 KB): [A 128x32][B 128x32] fp16, 64 B rows,
// swizzle chunk' = c ^ ((row>>1)&3). 6 stages (96 KB) = 3 groups of 2 (BK=64/iter).
// N-tile order rotated by CTA parity to decorrelate co-resident CTA phases.
#define STG_B 16384
#define NSTG  6

__device__ __forceinline__ int map_it(int it, int rot) {
    int t = ((it >> 5) + rot) & 7;
    return (t << 5) | (it & 31);
}

__device__ __forceinline__ void load_stage(unsigned sbuf, int m0, int it, int tid) {
    const int n0 = (it >> 5) << 7;
    const int k0 = (it & 31) << 5;
#pragma unroll
    for (int i = 0; i < 2; ++i) {                 // A: 512 chunks of 16B
        int cid = (i << 8) + tid;
        int row = cid >> 2, c = cid & 3;
        unsigned off = row * 64 + ((c ^ ((row >> 1) & 3)) << 4);
        cp16(sbuf + off, g_Ah + (size_t)(m0 + row) * D_K + k0 + c * 8);
    }
#pragma unroll
    for (int i = 0; i < 2; ++i) {                 // B: 512 chunks of 16B
        int cid = (i << 8) + tid;
        int row = cid >> 2, c = cid & 3;
        unsigned off = row * 64 + ((c ^ ((row >> 1) & 3)) << 4);
        cp16(sbuf + 8192 + off, g_WyT + (size_t)(n0 + row) * D_K + k0 + c * 8);
    }
}

__global__ void __launch_bounds__(256, 2) k_scores(const float* __restrict__ x,
                                                   const float* __restrict__ wv) {
    extern __shared__ uint8_t dsm[];
    __shared__ float sScore[2][128];

    const int tid = threadIdx.x, lane = tid & 31, warp = tid >> 5;
    const int wm = warp & 3, wn = warp >> 2;
    const int qr = lane >> 2, qc = (lane & 3) << 1;
    const int m0 = blockIdx.x << 7;
    const int b = m0 >> 11;
    const int g = lane >> 3, lr = lane & 7;
    const int rot = (blockIdx.x & 1) << 2;        // phase-stagger co-resident CTAs

    // ---- prologue: convert this CTA's 128 rows of x to fp16 in g_Ah ----
    {
        const float4* xsrc = reinterpret_cast<const float4*>(x + (size_t)m0 * D_K);
        __half2* adst = reinterpret_cast<__half2*>(g_Ah + (size_t)m0 * D_K);
#pragma unroll 4
        for (int i = tid; i < 32768; i += 256) {
            float4 v = xsrc[i];
            adst[2 * i]     = __floats2half2_rn(v.x, v.y);
            adst[2 * i + 1] = __floats2half2_rn(v.z, v.w);
        }
        __threadfence();
    }

    unsigned sbase;
    asm("{ .reg .u64 t; cvta.to.shared.u64 t, %1; cvt.u32.u64 %0, t; }"
        : "=r"(sbase) : "l"(dsm));

    unsigned aoff[2][2], boff[4][2];
#pragma unroll
    for (int mf = 0; mf < 2; ++mf) {
        int ml = wm * 32 + mf * 16 + (g & 1) * 8 + lr;
#pragma unroll
        for (int ks = 0; ks < 2; ++ks) {
            int c = 2 * ks + (g >> 1);
            aoff[mf][ks] = ml * 64 + ((c ^ ((ml >> 1) & 3)) << 4);
        }
    }
#pragma unroll
    for (int p = 0; p < 4; ++p) {
        int nl = wn * 64 + p * 16 + ((g >> 1) & 1) * 8 + lr;
#pragma unroll
        for (int ks = 0; ks < 2; ++ks) {
            int c = 2 * ks + (g & 1);
            boff[p][ks] = nl * 64 + ((c ^ ((nl >> 1) & 3)) << 4);
        }
    }

    sScore[tid >> 7][tid & 127] = 0.f;
    __syncthreads();        // prologue writes visible CTA-wide before cp.async

    load_stage(sbase, m0, map_it(0, rot), tid);
    load_stage(sbase + STG_B, m0, map_it(1, rot), tid);
    cp_commit();
    load_stage(sbase + 2 * STG_B, m0, map_it(2, rot), tid);
    load_stage(sbase + 3 * STG_B, m0, map_it(3, rot), tid);
    cp_commit();

    float acc[2][8][4];
#pragma unroll
    for (int mf = 0; mf < 2; ++mf)
#pragma unroll
        for (int nf = 0; nf < 8; ++nf)
#pragma unroll
            for (int q = 0; q < 4; ++q) acc[mf][nf][q] = 0.f;

    int s0 = 0;                         // ring slot of stage 2j
#pragma unroll 1
    for (int j = 0; j < 128; ++j) {
        cp_wait<1>();
        __syncthreads();
        if (j < 126) {
            int f = (s0 >= 2) ? s0 - 2 : s0 + 4;
            load_stage(sbase + f * STG_B, m0, map_it(2 * j + 4, rot), tid);
            load_stage(sbase + (f + 1) * STG_B, m0, map_it(2 * j + 5, rot), tid);
        }
        cp_commit();

#pragma unroll
        for (int half = 0; half < 2; ++half) {
            const unsigned sb = sbase + (s0 + half) * STG_B;
#pragma unroll
            for (int ks = 0; ks < 2; ++ks) {
                // batch ALL fragment loads for this k16 substep first
                unsigned ah[2][4], bb[4][4];
                ldmx4(ah[0], sb + aoff[0][ks]);
                ldmx4(ah[1], sb + aoff[1][ks]);
                ldmx4(bb[0], sb + 8192 + boff[0][ks]);
                ldmx4(bb[1], sb + 8192 + boff[1][ks]);
                ldmx4(bb[2], sb + 8192 + boff[2][ks]);
                ldmx4(bb[3], sb + 8192 + boff[3][ks]);
                // 16 mmas, all-distinct accumulators (no RAW inside substep)
#pragma unroll
                for (int p = 0; p < 4; ++p) {
                    mma_f16(acc[0][2 * p],     ah[0], bb[p][0], bb[p][1]);
                    mma_f16(acc[1][2 * p],     ah[1], bb[p][0], bb[p][1]);
                    mma_f16(acc[0][2 * p + 1], ah[0], bb[p][2], bb[p][3]);
                    mma_f16(acc[1][2 * p + 1], ah[1], bb[p][2], bb[p][3]);
                }
            }
        }
        s0 = (s0 == 4) ? 0 : s0 + 2;

        if ((j & 15) == 15) {                    // end of a 128-wide N-tile
            const int n0 = (((j >> 4) + rot) & 7) << 7;
#pragma unroll
            for (int mf = 0; mf < 2; ++mf) {
                float sa = 0.f, sb2 = 0.f;
#pragma unroll
                for (int nf = 0; nf < 8; ++nf) {
                    int gcol = n0 + wn * 64 + nf * 8 + qc;
                    float hp0 = __ldg(&g_hproj[b * D_N + gcol]);
                    float hp1 = __ldg(&g_hproj[b * D_N + gcol + 1]);
                    float w0 = __ldg(&wv[gcol]), w1 = __ldg(&wv[gcol + 1]);
                    sa  += fmaxf(acc[mf][nf][0] + hp0, 0.f) * w0
                         + fmaxf(acc[mf][nf][1] + hp1, 0.f) * w1;
                    sb2 += fmaxf(acc[mf][nf][2] + hp0, 0.f) * w0
                         + fmaxf(acc[mf][nf][3] + hp1, 0.f) * w1;
                }
                sa  += __shfl_xor_sync(0xffffffffu, sa, 1);
                sa  += __shfl_xor_sync(0xffffffffu, sa, 2);
                sb2 += __shfl_xor_sync(0xffffffffu, sb2, 1);
                sb2 += __shfl_xor_sync(0xffffffffu, sb2, 2);
                if ((lane & 3) == 0) {
                    int r0 = wm * 32 + mf * 16 + qr;
                    sScore[wn][r0]     += sa;
                    sScore[wn][r0 + 8] += sb2;
                }
#pragma unroll
                for (int nf = 0; nf < 8; ++nf)
#pragma unroll
                    for (int q = 0; q < 4; ++q) acc[mf][nf][q] = 0.f;
            }
        }
    }

    __syncthreads();
    if (tid < 128) g_scores[m0 + tid] = sScore[0][tid] + sScore[1][tid];
}

// ---- softmax over T --------------------------------------------------------------
__global__ void k_softmax() {
    int b = blockIdx.x, tid = threadIdx.x;
    __shared__ float red[256];
    float m = -1e30f;
    for (int t = tid; t < N_T; t += 256) m = fmaxf(m, g_scores[b * N_T + t]);
    red[tid] = m; __syncthreads();
    for (int s = 128; s > 0; s >>= 1) {
        if (tid < s) red[tid] = fmaxf(red[tid], red[tid + s]);
        __syncthreads();
    }
    float mx = red[0]; __syncthreads();
    float sum = 0.f;
    for (int t = tid; t < N_T; t += 256) {
        float e = __expf(g_scores[b * N_T + t] - mx);
        g_alpha[b * N_T + t] = e;
        sum += e;
    }
    red[tid] = sum; __syncthreads();
    for (int s = 128; s > 0; s >>= 1) {
        if (tid < s) red[tid] += red[tid + s];
        __syncthreads();
    }
    float inv = 1.0f / red[0];
    for (int t = tid; t < N_T; t += 256) g_alpha[b * N_T + t] *= inv;
}

// ---- r partials (half2-vectorized) --------------------------------------------------
__global__ void k_rpart() {
    int d2 = blockIdx.x * 256 + threadIdx.x;     // half2 column index (0..511)
    int b = blockIdx.y, p = blockIdx.z;
    __shared__ float sAl[256];
    sAl[threadIdx.x] = g_alpha[b * N_T + p * 256 + threadIdx.x];
    __syncthreads();
    const __half2* xp = reinterpret_cast<const __half2*>(
        g_Ah + ((size_t)b * N_T + p * 256) * D_K) + d2;
    float ax = 0.f, ay = 0.f;
#pragma unroll 8
    for (int i = 0; i < 256; ++i) {
        float2 f = __half22float2(xp[(size_t)i * 512]);
        float a = sAl[i];
        ax += a * f.x;
        ay += a * f.y;
    }
    float* dst = g_rpart + (p * N_B + b) * D_K + 2 * d2;
    dst[0] = ax;
    dst[1] = ay;
}

// ---- out = relu(r @ Wp + last @ Wx) ---------------------------------------------------
__global__ void k_final(const float* __restrict__ last, const float* __restrict__ Wp,
                        const float* __restrict__ Wx, float* __restrict__ out) {
    int e = blockIdx.x * 256 + threadIdx.x;
    int b = blockIdx.y;
    __shared__ float sR[D_K], sL[D_K];
    for (int i = threadIdx.x; i < D_K; i += 256) {
        float r = 0.f;
#pragma unroll
        for (int p = 0; p < 8; ++p) r += g_rpart[(p * N_B + b) * D_K + i];
        sR[i] = r;
        sL[i] = last[b * D_K + i];
    }
    __syncthreads();
    float acc = 0.f;
#pragma unroll 4
    for (int k = 0; k < D_K; ++k)
        acc += sR[k] * Wp[(size_t)k * D_N + e] + sL[k] * Wx[(size_t)k * D_N + e];
    out[b * D_N + e] = fmaxf(acc, 0.f);
}

// ---- launch ----------------------------------------------------------------------------
extern "C" void kernel_launch(void* const* d_in, const int* in_sizes, int n_in,
                              void* d_out, int out_size) {
    const float* x    = (const float*)d_in[0];
    const float* last = (const float*)d_in[1];
    const float* Wy   = (const float*)d_in[2];
    const float* Wh   = (const float*)d_in[3];
    const float* wv   = (const float*)d_in[4];
    const float* Wp   = (const float*)d_in[5];
    const float* Wx   = (const float*)d_in[6];
    float* out = (float*)d_out;

    static bool attr_set = false;
    if (!attr_set) {
        cudaFuncSetAttribute(k_scores, cudaFuncAttributeMaxDynamicSharedMemorySize,
                             NSTG * STG_B);
        attr_set = true;
    }

    k_split_wy<<<dim3(32, 32), dim3(32, 32)>>>(Wy);
    k_hproj<<<dim3(4, N_B), 256>>>(last, Wh);
    k_scores<<<N_M / 128, 256, NSTG * STG_B>>>(x, wv);
    k_softmax<<<N_B, 256>>>();
    k_rpart<<<dim3(2, N_B, 8), 256>>>();
    k_final<<<dim3(4, N_B), 256>>>(last, Wp, Wx, out);
}

// round 17
// speedup vs baseline: 1.3512x; 1.1314x over previous
#include <cuda_runtime.h>
#include <cuda_fp16.h>
#include <cstdint>

#define D_K 1024
#define D_N 1024
#define N_B 32
#define N_T 2048
#define N_M (N_B * N_T)

__device__ __half g_Ah[(size_t)N_M * D_K];      // x in fp16 (written by k_scores prologue)
__device__ __half g_WyT[(size_t)D_N * D_K];     // Wy^T in fp16 [n][k]
__device__ float g_hppart[4 * N_B * D_N];       // hproj k-partials
__device__ float g_scores[N_M];
__device__ float g_alpha[N_M];
__device__ float g_rpart[8 * N_B * D_K];
__device__ float g_opart[4 * N_B * D_N];        // final k-partials

__device__ __forceinline__ void mma_f16(float* c, const unsigned* a,
                                        unsigned b0, unsigned b1) {
    asm volatile(
        "mma.sync.aligned.m16n8k16.row.col.f32.f16.f16.f32 "
        "{%0,%1,%2,%3}, {%4,%5,%6,%7}, {%8,%9}, {%0,%1,%2,%3};\n"
        : "+f"(c[0]), "+f"(c[1]), "+f"(c[2]), "+f"(c[3])
        : "r"(a[0]), "r"(a[1]), "r"(a[2]), "r"(a[3]), "r"(b0), "r"(b1));
}
__device__ __forceinline__ void ldmx4(unsigned* r, unsigned addr) {
    asm volatile("ldmatrix.sync.aligned.m8n8.x4.shared.b16 {%0,%1,%2,%3}, [%4];"
                 : "=r"(r[0]), "=r"(r[1]), "=r"(r[2]), "=r"(r[3]) : "r"(addr));
}
__device__ __forceinline__ void cp16(unsigned dst, const void* src) {
    asm volatile("cp.async.cg.shared.global [%0], [%1], 16;\n" :: "r"(dst), "l"(src));
}
__device__ __forceinline__ void cp_commit() { asm volatile("cp.async.commit_group;\n"); }
template <int N> __device__ __forceinline__ void cp_wait() {
    asm volatile("cp.async.wait_group %0;\n" :: "n"(N));
}

// ---- transpose Wy -> WyT fp16 [n][k] -----------------------------------------
__global__ void k_split_wy(const float* __restrict__ Wy) {
    __shared__ float tile[32][33];
    int k = blockIdx.y * 32 + threadIdx.y;
    int n = blockIdx.x * 32 + threadIdx.x;
    tile[threadIdx.y][threadIdx.x] = Wy[(size_t)k * D_N + n];
    __syncthreads();
    int nn = blockIdx.x * 32 + threadIdx.y;
    int kk = blockIdx.y * 32 + threadIdx.x;
    g_WyT[(size_t)nn * D_K + kk] = __float2half_rn(tile[threadIdx.x][threadIdx.y]);
}

// ---- hproj partials: g_hppart[kp][b][e] = sum_{k in part} last[b][k] Wh[k][e] ----
__global__ void k_hproj(const float* __restrict__ last, const float* __restrict__ Wh) {
    const int kp = blockIdx.x, b = blockIdx.y, t = threadIdx.x;
    __shared__ float sL[256];
    sL[t] = last[b * D_K + kp * 256 + t];
    __syncthreads();
    float4 acc = make_float4(0.f, 0.f, 0.f, 0.f);
    const float4* W = reinterpret_cast<const float4*>(Wh + (size_t)(kp * 256) * D_N) + t;
#pragma unroll 8
    for (int kk = 0; kk < 256; ++kk) {
        float4 w = W[(size_t)kk * 256];
        float l = sL[kk];
        acc.x += l * w.x; acc.y += l * w.y; acc.z += l * w.z; acc.w += l * w.w;
    }
    *reinterpret_cast<float4*>(g_hppart + ((kp * N_B) + b) * D_N + 4 * t) = acc;
}

// ---- fused fp16 GEMM -> scores (in-kernel x->fp16 conversion) --------------------
#define STG_B 16384
#define NSTG  6

__device__ __forceinline__ int map_it(int it, int rot) {
    int t = ((it >> 5) + rot) & 7;
    return (t << 5) | (it & 31);
}

__device__ __forceinline__ void load_stage(unsigned sbuf, int m0, int it, int tid) {
    const int n0 = (it >> 5) << 7;
    const int k0 = (it & 31) << 5;
#pragma unroll
    for (int i = 0; i < 2; ++i) {                 // A: 512 chunks of 16B
        int cid = (i << 8) + tid;
        int row = cid >> 2, c = cid & 3;
        unsigned off = row * 64 + ((c ^ ((row >> 1) & 3)) << 4);
        cp16(sbuf + off, g_Ah + (size_t)(m0 + row) * D_K + k0 + c * 8);
    }
#pragma unroll
    for (int i = 0; i < 2; ++i) {                 // B: 512 chunks of 16B
        int cid = (i << 8) + tid;
        int row = cid >> 2, c = cid & 3;
        unsigned off = row * 64 + ((c ^ ((row >> 1) & 3)) << 4);
        cp16(sbuf + 8192 + off, g_WyT + (size_t)(n0 + row) * D_K + k0 + c * 8);
    }
}

__global__ void __launch_bounds__(256, 2) k_scores(const float* __restrict__ x,
                                                   const float* __restrict__ wv) {
    extern __shared__ uint8_t dsm[];
    __shared__ float sScore[2][128];

    const int tid = threadIdx.x, lane = tid & 31, warp = tid >> 5;
    const int wm = warp & 3, wn = warp >> 2;
    const int qr = lane >> 2, qc = (lane & 3) << 1;
    const int m0 = blockIdx.x << 7;
    const int b = m0 >> 11;
    const int g = lane >> 3, lr = lane & 7;
    const int rot = (blockIdx.x & 1) << 2;

    // ---- prologue: convert this CTA's 128 rows of x to fp16 in g_Ah ----
    {
        const float4* xsrc = reinterpret_cast<const float4*>(x + (size_t)m0 * D_K);
        __half2* adst = reinterpret_cast<__half2*>(g_Ah + (size_t)m0 * D_K);
#pragma unroll 4
        for (int i = tid; i < 32768; i += 256) {
            float4 v = xsrc[i];
            adst[2 * i]     = __floats2half2_rn(v.x, v.y);
            adst[2 * i + 1] = __floats2half2_rn(v.z, v.w);
        }
        __threadfence();
    }

    unsigned sbase;
    asm("{ .reg .u64 t; cvta.to.shared.u64 t, %1; cvt.u32.u64 %0, t; }"
        : "=r"(sbase) : "l"(dsm));

    unsigned aoff[2][2], boff[4][2];
#pragma unroll
    for (int mf = 0; mf < 2; ++mf) {
        int ml = wm * 32 + mf * 16 + (g & 1) * 8 + lr;
#pragma unroll
        for (int ks = 0; ks < 2; ++ks) {
            int c = 2 * ks + (g >> 1);
            aoff[mf][ks] = ml * 64 + ((c ^ ((ml >> 1) & 3)) << 4);
        }
    }
#pragma unroll
    for (int p = 0; p < 4; ++p) {
        int nl = wn * 64 + p * 16 + ((g >> 1) & 1) * 8 + lr;
#pragma unroll
        for (int ks = 0; ks < 2; ++ks) {
            int c = 2 * ks + (g & 1);
            boff[p][ks] = nl * 64 + ((c ^ ((nl >> 1) & 3)) << 4);
        }
    }

    sScore[tid >> 7][tid & 127] = 0.f;
    __syncthreads();

    load_stage(sbase, m0, map_it(0, rot), tid);
    load_stage(sbase + STG_B, m0, map_it(1, rot), tid);
    cp_commit();
    load_stage(sbase + 2 * STG_B, m0, map_it(2, rot), tid);
    load_stage(sbase + 3 * STG_B, m0, map_it(3, rot), tid);
    cp_commit();

    float acc[2][8][4];
#pragma unroll
    for (int mf = 0; mf < 2; ++mf)
#pragma unroll
        for (int nf = 0; nf < 8; ++nf)
#pragma unroll
            for (int q = 0; q < 4; ++q) acc[mf][nf][q] = 0.f;

    int s0 = 0;
#pragma unroll 1
    for (int j = 0; j < 128; ++j) {
        cp_wait<1>();
        __syncthreads();
        if (j < 126) {
            int f = (s0 >= 2) ? s0 - 2 : s0 + 4;
            load_stage(sbase + f * STG_B, m0, map_it(2 * j + 4, rot), tid);
            load_stage(sbase + (f + 1) * STG_B, m0, map_it(2 * j + 5, rot), tid);
        }
        cp_commit();

#pragma unroll
        for (int half = 0; half < 2; ++half) {
            const unsigned sb = sbase + (s0 + half) * STG_B;
#pragma unroll
            for (int ks = 0; ks < 2; ++ks) {
                unsigned ah[2][4], bb[4][4];
                ldmx4(ah[0], sb + aoff[0][ks]);
                ldmx4(ah[1], sb + aoff[1][ks]);
                ldmx4(bb[0], sb + 8192 + boff[0][ks]);
                ldmx4(bb[1], sb + 8192 + boff[1][ks]);
                ldmx4(bb[2], sb + 8192 + boff[2][ks]);
                ldmx4(bb[3], sb + 8192 + boff[3][ks]);
#pragma unroll
                for (int p = 0; p < 4; ++p) {
                    mma_f16(acc[0][2 * p],     ah[0], bb[p][0], bb[p][1]);
                    mma_f16(acc[1][2 * p],     ah[1], bb[p][0], bb[p][1]);
                    mma_f16(acc[0][2 * p + 1], ah[0], bb[p][2], bb[p][3]);
                    mma_f16(acc[1][2 * p + 1], ah[1], bb[p][2], bb[p][3]);
                }
            }
        }
        s0 = (s0 == 4) ? 0 : s0 + 2;

        if ((j & 15) == 15) {
            const int n0 = (((j >> 4) + rot) & 7) << 7;
#pragma unroll
            for (int mf = 0; mf < 2; ++mf) {
                float sa = 0.f, sb2 = 0.f;
#pragma unroll
                for (int nf = 0; nf < 8; ++nf) {
                    int gcol = n0 + wn * 64 + nf * 8 + qc;
                    // hproj = sum of 4 k-partials (L2-hot, deterministic order)
                    float hp0 = __ldg(&g_hppart[b * D_N + gcol])
                              + __ldg(&g_hppart[(N_B + b) * D_N + gcol])
                              + __ldg(&g_hppart[(2 * N_B + b) * D_N + gcol])
                              + __ldg(&g_hppart[(3 * N_B + b) * D_N + gcol]);
                    float hp1 = __ldg(&g_hppart[b * D_N + gcol + 1])
                              + __ldg(&g_hppart[(N_B + b) * D_N + gcol + 1])
                              + __ldg(&g_hppart[(2 * N_B + b) * D_N + gcol + 1])
                              + __ldg(&g_hppart[(3 * N_B + b) * D_N + gcol + 1]);
                    float w0 = __ldg(&wv[gcol]), w1 = __ldg(&wv[gcol + 1]);
                    sa  += fmaxf(acc[mf][nf][0] + hp0, 0.f) * w0
                         + fmaxf(acc[mf][nf][1] + hp1, 0.f) * w1;
                    sb2 += fmaxf(acc[mf][nf][2] + hp0, 0.f) * w0
                         + fmaxf(acc[mf][nf][3] + hp1, 0.f) * w1;
                }
                sa  += __shfl_xor_sync(0xffffffffu, sa, 1);
                sa  += __shfl_xor_sync(0xffffffffu, sa, 2);
                sb2 += __shfl_xor_sync(0xffffffffu, sb2, 1);
                sb2 += __shfl_xor_sync(0xffffffffu, sb2, 2);
                if ((lane & 3) == 0) {
                    int r0 = wm * 32 + mf * 16 + qr;
                    sScore[wn][r0]     += sa;
                    sScore[wn][r0 + 8] += sb2;
                }
#pragma unroll
                for (int nf = 0; nf < 8; ++nf)
#pragma unroll
                    for (int q = 0; q < 4; ++q) acc[mf][nf][q] = 0.f;
            }
        }
    }

    __syncthreads();
    if (tid < 128) g_scores[m0 + tid] = sScore[0][tid] + sScore[1][tid];
}

// ---- softmax over T --------------------------------------------------------------
__global__ void k_softmax() {
    int b = blockIdx.x, tid = threadIdx.x;
    __shared__ float red[256];
    float m = -1e30f;
    for (int t = tid; t < N_T; t += 256) m = fmaxf(m, g_scores[b * N_T + t]);
    red[tid] = m; __syncthreads();
    for (int s = 128; s > 0; s >>= 1) {
        if (tid < s) red[tid] = fmaxf(red[tid], red[tid + s]);
        __syncthreads();
    }
    float mx = red[0]; __syncthreads();
    float sum = 0.f;
    for (int t = tid; t < N_T; t += 256) {
        float e = __expf(g_scores[b * N_T + t] - mx);
        g_alpha[b * N_T + t] = e;
        sum += e;
    }
    red[tid] = sum; __syncthreads();
    for (int s = 128; s > 0; s >>= 1) {
        if (tid < s) red[tid] += red[tid + s];
        __syncthreads();
    }
    float inv = 1.0f / red[0];
    for (int t = tid; t < N_T; t += 256) g_alpha[b * N_T + t] *= inv;
}

// ---- r partials (half2-vectorized) --------------------------------------------------
__global__ void k_rpart() {
    int d2 = blockIdx.x * 256 + threadIdx.x;
    int b = blockIdx.y, p = blockIdx.z;
    __shared__ float sAl[256];
    sAl[threadIdx.x] = g_alpha[b * N_T + p * 256 + threadIdx.x];
    __syncthreads();
    const __half2* xp = reinterpret_cast<const __half2*>(
        g_Ah + ((size_t)b * N_T + p * 256) * D_K) + d2;
    float ax = 0.f, ay = 0.f;
#pragma unroll 8
    for (int i = 0; i < 256; ++i) {
        float2 f = __half22float2(xp[(size_t)i * 512]);
        float a = sAl[i];
        ax += a * f.x;
        ay += a * f.y;
    }
    float* dst = g_rpart + (p * N_B + b) * D_K + 2 * d2;
    dst[0] = ax;
    dst[1] = ay;
}

// ---- final partials: g_opart[kp][b][e] = sum_{k in part} r[b][k]Wp[k][e]+last[b][k]Wx[k][e]
__global__ void k_final(const float* __restrict__ last, const float* __restrict__ Wp,
                        const float* __restrict__ Wx) {
    const int kp = blockIdx.x, b = blockIdx.y, t = threadIdx.x;
    __shared__ float sR[256], sL[256];
    {
        int k = kp * 256 + t;
        float r = 0.f;
#pragma unroll
        for (int p = 0; p < 8; ++p) r += g_rpart[(p * N_B + b) * D_K + k];
        sR[t] = r;
        sL[t] = last[b * D_K + k];
    }
    __syncthreads();
    float4 acc = make_float4(0.f, 0.f, 0.f, 0.f);
    const float4* Pp = reinterpret_cast<const float4*>(Wp + (size_t)(kp * 256) * D_N) + t;
    const float4* Px = reinterpret_cast<const float4*>(Wx + (size_t)(kp * 256) * D_N) + t;
#pragma unroll 8
    for (int kk = 0; kk < 256; ++kk) {
        float4 wp = Pp[(size_t)kk * 256];
        float4 wx = Px[(size_t)kk * 256];
        float r = sR[kk], l = sL[kk];
        acc.x += r * wp.x + l * wx.x;
        acc.y += r * wp.y + l * wx.y;
        acc.z += r * wp.z + l * wx.z;
        acc.w += r * wp.w + l * wx.w;
    }
    *reinterpret_cast<float4*>(g_opart + ((kp * N_B) + b) * D_N + 4 * t) = acc;
}

// ---- out = relu(sum of 4 k-partials) -----------------------------------------------
__global__ void k_out(float* __restrict__ out) {
    const int b = blockIdx.x, t = threadIdx.x;
    float4 a0 = *reinterpret_cast<const float4*>(g_opart + b * D_N + 4 * t);
    float4 a1 = *reinterpret_cast<const float4*>(g_opart + (N_B + b) * D_N + 4 * t);
    float4 a2 = *reinterpret_cast<const float4*>(g_opart + (2 * N_B + b) * D_N + 4 * t);
    float4 a3 = *reinterpret_cast<const float4*>(g_opart + (3 * N_B + b) * D_N + 4 * t);
    float4 r;
    r.x = fmaxf(a0.x + a1.x + a2.x + a3.x, 0.f);
    r.y = fmaxf(a0.y + a1.y + a2.y + a3.y, 0.f);
    r.z = fmaxf(a0.z + a1.z + a2.z + a3.z, 0.f);
    r.w = fmaxf(a0.w + a1.w + a2.w + a3.w, 0.f);
    *reinterpret_cast<float4*>(out + b * D_N + 4 * t) = r;
}

// ---- launch ----------------------------------------------------------------------------
extern "C" void kernel_launch(void* const* d_in, const int* in_sizes, int n_in,
                              void* d_out, int out_size) {
    const float* x    = (const float*)d_in[0];
    const float* last = (const float*)d_in[1];
    const float* Wy   = (const float*)d_in[2];
    const float* Wh   = (const float*)d_in[3];
    const float* wv   = (const float*)d_in[4];
    const float* Wp   = (const float*)d_in[5];
    const float* Wx   = (const float*)d_in[6];
    float* out = (float*)d_out;

    static bool attr_set = false;
    if (!attr_set) {
        cudaFuncSetAttribute(k_scores, cudaFuncAttributeMaxDynamicSharedMemorySize,
                             NSTG * STG_B);
        attr_set = true;
    }

    k_split_wy<<<dim3(32, 32), dim3(32, 32)>>>(Wy);
    k_hproj<<<dim3(4, N_B), 256>>>(last, Wh);
    k_scores<<<N_M / 128, 256, NSTG * STG_B>>>(x, wv);
    k_softmax<<<N_B, 256>>>();
    k_rpart<<<dim3(2, N_B, 8), 256>>>();
    k_final<<<dim3(4, N_B), 256>>>(last, Wp, Wx);
    k_out<<<N_B, 256>>>(out);
}